// round 11
// baseline (speedup 1.0000x reference)
#include <cuda_runtime.h>

#define Bn 4
#define Cn 64
#define Hn 128
#define Wn 128
#define HWn (Hn*Wn)

// ---------------- scratch (device globals; no runtime allocation) ----------------
__device__ __align__(16) float g_xT[Bn*HWn*Cn];       // x  in [B,H,W,C]
__device__ __align__(16) float g_interT[Bn*HWn*Cn];   // inter in [B,H,W,C]
__device__ __align__(16) float g_om[Bn*HWn*32];       // offsets+mask, pixel-major, pad 32
__device__ __align__(16) float g_woffT[1152*32];      // [r=cin*9+tap][o(pad32)]
__device__ __align__(16) float g_wdcnT[576*64];       // [r=c*9+k][o]
__device__ __align__(16) float g_wg1T[4096];          // [c][o]
__device__ __align__(16) float g_wg2T[4096];
__device__ __align__(16) float g_wb1T[4096];
__device__ __align__(16) float g_wb2T[4096];

// ---------------- weight prep ----------------
__global__ void prep_weights(const float* __restrict__ w_off,
                             const float* __restrict__ w_dcn,
                             const float* __restrict__ wg1, const float* __restrict__ wg2,
                             const float* __restrict__ wb1, const float* __restrict__ wb2) {
    int idx = blockIdx.x * blockDim.x + threadIdx.x;
    if (idx < 1152*32) {
        int r = idx >> 5, o = idx & 31;
        g_woffT[idx] = (o < 27) ? w_off[o*1152 + r] : 0.f;
    }
    if (idx < 576*64) {
        int r = idx >> 6, o = idx & 63;
        g_wdcnT[idx] = w_dcn[o*576 + r];
    }
    if (idx < 4096) {
        int c = idx >> 6, o = idx & 63;
        g_wg1T[idx] = wg1[o*64 + c];
        g_wg2T[idx] = wg2[o*64 + c];
        g_wb1T[idx] = wb1[o*64 + c];
        g_wb2T[idx] = wb2[o*64 + c];
    }
}

// ---------------- NCHW -> NHWC transpose ----------------
__global__ void transpose_k(const float* __restrict__ in, int which) {
    __shared__ float tile[32][33];
    float* out = which ? g_interT : g_xT;
    int b = blockIdx.z;
    int n0 = blockIdx.x * 32;
    int c0 = blockIdx.y * 32;
    int tx = threadIdx.x, ty = threadIdx.y;
    const float* src = in + (size_t)b * Cn * HWn;
    float* dst = out + (size_t)b * HWn * Cn;
#pragma unroll
    for (int i = 0; i < 32; i += 8)
        tile[ty + i][tx] = src[(size_t)(c0 + ty + i) * HWn + n0 + tx];
    __syncthreads();
#pragma unroll
    for (int i = 0; i < 32; i += 8)
        dst[(size_t)(n0 + ty + i) * Cn + c0 + tx] = tile[tx][ty + i];
}

// ---------------- offset conv ----------------
// block: 256 thr = 8 o-groups(4 out) x 32 lanes(2 px each) -> 64 pixels x 32 outputs
// staged in 32-channel chunks: smem 32ch x 3rows x 66cols = 25344 B (static)
__global__ __launch_bounds__(256) void offset_conv_k(
    const float* __restrict__ x, const float* __restrict__ inter,
    const float* __restrict__ b_off) {
    __shared__ __align__(16) float s_in[32 * 198];   // [ci][ry(3)][cx(66)]
    int b = blockIdx.z, h = blockIdx.y, w0 = blockIdx.x * 64;
    int tid = threadIdx.x;
    int og = tid >> 5, lane = tid & 31;
    int o0 = og * 4, p0 = lane * 2;
    float acc0[4] = {0.f,0.f,0.f,0.f};   // pixel p0
    float acc1[4] = {0.f,0.f,0.f,0.f};   // pixel p0+1

    for (int half = 0; half < 2; ++half) {
        const float* src = half ? inter : x;
        for (int chunk = 0; chunk < 2; ++chunk) {
            int cbase = chunk * 32;
            __syncthreads();
            for (int idx = tid; idx < 32 * 198; idx += 256) {
                int ci = idx / 198; int rem = idx - ci * 198;
                int ry = rem / 66;  int cx = rem - ry * 66;
                int y = h - 1 + ry, xw = w0 - 1 + cx;
                float v = 0.f;
                if ((unsigned)y < (unsigned)Hn && (unsigned)xw < (unsigned)Wn)
                    v = src[((size_t)(b * Cn + cbase + ci) * Hn + y) * Wn + xw];
                s_in[idx] = v;
            }
            __syncthreads();
            const float* wb = g_woffT + (half * 64 + cbase) * 288 + o0;
            for (int ci = 0; ci < 32; ++ci) {
                const float* srow = s_in + ci * 198 + p0;
                // 3x4 input patch for this thread's 2 pixels (6 x LDS.64)
                float v[3][4];
#pragma unroll
                for (int ry = 0; ry < 3; ++ry) {
                    float2 u0 = *(const float2*)(srow + ry * 66);
                    float2 u1 = *(const float2*)(srow + ry * 66 + 2);
                    v[ry][0] = u0.x; v[ry][1] = u0.y;
                    v[ry][2] = u1.x; v[ry][3] = u1.y;
                }
                const float* wr = wb + ci * 288;
#pragma unroll
                for (int tap = 0; tap < 9; ++tap) {
                    float4 w4 = *(const float4*)(wr + tap * 32);
                    int ry = tap / 3, kx = tap - ry * 3;
                    float s0 = v[ry][kx];
                    float s1 = v[ry][kx + 1];
                    acc0[0] += w4.x * s0; acc0[1] += w4.y * s0;
                    acc0[2] += w4.z * s0; acc0[3] += w4.w * s0;
                    acc1[0] += w4.x * s1; acc1[1] += w4.y * s1;
                    acc1[2] += w4.z * s1; acc1[3] += w4.w * s1;
                }
            }
        }
    }

    float bj[4];
#pragma unroll
    for (int j = 0; j < 4; ++j) bj[j] = (o0 + j < 27) ? b_off[o0 + j] : 0.f;

    size_t pixbase = ((size_t)b * Hn + h) * Wn + w0;
#pragma unroll
    for (int px = 0; px < 2; ++px) {
        float* a = px ? acc1 : acc0;
        float4 r;
        float* rv = (float*)&r;
#pragma unroll
        for (int j = 0; j < 4; ++j) {
            int o = o0 + j;
            float vv = a[j] + bj[j];
            if (o >= 18 && o < 27) vv = 1.f / (1.f + expf(-vv));
            rv[j] = vv;
        }
        *(float4*)(g_om + (pixbase + p0 + px) * 32 + o0) = r;
    }
}

__device__ __forceinline__ float lrelu(float v) { return v >= 0.f ? v : 0.1f * v; }

// ---------------- fused: SFT chains + deformable sampling + DCN + residual ----
// block covers 32 pixels. 256 thr = 16 o-groups(4 out) x 16 t(2 px each: 2t, 2t+1)
// dynamic smem: s_samp [576][34] + s_om [32][27]  = 81792 B
__global__ __launch_bounds__(256) void fused_k(float* __restrict__ out) {
    extern __shared__ __align__(16) float smem[];
    float* s_samp = smem;                  // [576][34]
    float* s_om   = smem + 576 * 34;       // [32][27]
    // aliased into s_samp (dead before sampling writes it):
    float* s_iv = smem;                    // [32][65]
    float* s_t1 = smem + 2080;             // [32][67]
    float* s_t2 = smem + 2080 + 2144;      // [32][67]

    int b = blockIdx.z, h = blockIdx.y, w0 = blockIdx.x * 32;
    int tid = threadIdx.x;
    int og = tid >> 4, t = tid & 15, o0 = og * 4;
    int px0 = 2 * t, px1 = 2 * t + 1;
    size_t pixbase = ((size_t)b * Hn + h) * Wn + w0;

    // load om (27/px) and inter vectors (64/px)
    for (int idx = tid; idx < 32 * 27; idx += 256) {
        int pp = idx / 27, c = idx - pp * 27;
        s_om[idx] = g_om[(pixbase + pp) * 32 + c];
    }
    for (int idx = tid; idx < 32 * 64; idx += 256) {
        int pp = idx >> 6, c = idx & 63;
        s_iv[pp * 65 + c] = g_interT[(pixbase + pp) * 64 + c];
    }
    __syncthreads();

    // stage 1: t1 = lrelu(w_g1 @ iv), t2 = lrelu(w_b1 @ iv)   (2 pixels/thread)
    float a1[2][4] = {{0}}, a2[2][4] = {{0}};
#pragma unroll 4
    for (int c = 0; c < 64; ++c) {
        float v0 = s_iv[px0 * 65 + c];
        float v1 = s_iv[px1 * 65 + c];
        float4 w1 = *(const float4*)(g_wg1T + c * 64 + o0);
        float4 w2 = *(const float4*)(g_wb1T + c * 64 + o0);
        a1[0][0] += w1.x * v0; a1[0][1] += w1.y * v0; a1[0][2] += w1.z * v0; a1[0][3] += w1.w * v0;
        a1[1][0] += w1.x * v1; a1[1][1] += w1.y * v1; a1[1][2] += w1.z * v1; a1[1][3] += w1.w * v1;
        a2[0][0] += w2.x * v0; a2[0][1] += w2.y * v0; a2[0][2] += w2.z * v0; a2[0][3] += w2.w * v0;
        a2[1][0] += w2.x * v1; a2[1][1] += w2.y * v1; a2[1][2] += w2.z * v1; a2[1][3] += w2.w * v1;
    }
#pragma unroll
    for (int px = 0; px < 2; ++px) {
        float* t1p = s_t1 + (2 * t + px) * 67 + o0;
        float* t2p = s_t2 + (2 * t + px) * 67 + o0;
#pragma unroll
        for (int j = 0; j < 4; ++j) { t1p[j] = lrelu(a1[px][j]); t2p[j] = lrelu(a2[px][j]); }
    }
    __syncthreads();

    // stage 2: gamma = w_g2 @ t1, beta = w_b2 @ t2 (kept in regs)
    float gm[2][4] = {{0}}, bt[2][4] = {{0}};
#pragma unroll 4
    for (int c = 0; c < 64; ++c) {
        float u0 = s_t1[px0 * 67 + c];
        float u1 = s_t1[px1 * 67 + c];
        float v0 = s_t2[px0 * 67 + c];
        float v1 = s_t2[px1 * 67 + c];
        float4 w1 = *(const float4*)(g_wg2T + c * 64 + o0);
        float4 w2 = *(const float4*)(g_wb2T + c * 64 + o0);
        gm[0][0] += w1.x * u0; gm[0][1] += w1.y * u0; gm[0][2] += w1.z * u0; gm[0][3] += w1.w * u0;
        gm[1][0] += w1.x * u1; gm[1][1] += w1.y * u1; gm[1][2] += w1.z * u1; gm[1][3] += w1.w * u1;
        bt[0][0] += w2.x * v0; bt[0][1] += w2.y * v0; bt[0][2] += w2.z * v0; bt[0][3] += w2.w * v0;
        bt[1][0] += w2.x * v1; bt[1][1] += w2.y * v1; bt[1][2] += w2.z * v1; bt[1][3] += w2.w * v1;
    }
    __syncthreads();   // aliased region reads done before sampling overwrites

    // sampling: s_samp[(c*9+k)*34 + pp] = bilinear(x, pp, k) * mask
    int wi = tid >> 5, lane = tid & 31;
    for (int task = wi; task < 32 * 9; task += 8) {
        int pp = task / 9, k = task - pp * 9;
        float dy = s_om[pp * 27 + k];
        float dx = s_om[pp * 27 + 9 + k];
        float m  = s_om[pp * 27 + 18 + k];
        int ky = k / 3, kx = k - ky * 3;
        float py = (float)(h + ky - 1) + dy;
        float pxc = (float)(w0 + pp + kx - 1) + dx;
        float fy = floorf(py), fx = floorf(pxc);
        float wy = py - fy, wx = pxc - fx;
        int y0 = (int)fy, x0 = (int)fx;
        bool vy0 = (unsigned)y0 < (unsigned)Hn;
        bool vy1 = (unsigned)(y0 + 1) < (unsigned)Hn;
        bool vx0 = (unsigned)x0 < (unsigned)Wn;
        bool vx1 = (unsigned)(x0 + 1) < (unsigned)Wn;
        float w00 = (1.f - wy) * (1.f - wx) * m;
        float w01 = (1.f - wy) * wx * m;
        float w10 = wy * (1.f - wx) * m;
        float w11 = wy * wx * m;
        const float* xb = g_xT + (size_t)b * HWn * Cn
                          + ((long long)y0 * Wn + x0) * Cn;
#pragma unroll
        for (int cc = 0; cc < 2; ++cc) {
            int c = lane + cc * 32;
            float v00 = (vy0 && vx0) ? xb[c] : 0.f;
            float v01 = (vy0 && vx1) ? xb[c + Cn] : 0.f;
            float v10 = (vy1 && vx0) ? xb[c + Wn * Cn] : 0.f;
            float v11 = (vy1 && vx1) ? xb[c + Wn * Cn + Cn] : 0.f;
            float val = v00 * w00 + v01 * w01 + v10 * w10 + v11 * w11;
            s_samp[(c * 9 + k) * 34 + pp] = val;
        }
    }
    __syncthreads();

    // DCN: d[px][o] = sum_r wdcnT[r][o] * samp[r][px]   (LDS.64 pixel pair)
    float d[2][4] = {{0}};
#pragma unroll 4
    for (int r = 0; r < 576; ++r) {
        float4 w4 = *(const float4*)(g_wdcnT + r * 64 + o0);
        float2 sp = *(const float2*)(s_samp + r * 34 + px0);
        d[0][0] += w4.x * sp.x; d[0][1] += w4.y * sp.x; d[0][2] += w4.z * sp.x; d[0][3] += w4.w * sp.x;
        d[1][0] += w4.x * sp.y; d[1][1] += w4.y * sp.y; d[1][2] += w4.z * sp.y; d[1][3] += w4.w * sp.y;
    }

    // epilogue: out = x + dcn + x*gamma + beta   (NCHW, float2 across pixel pair)
    float4 xv0 = *(const float4*)(g_xT + (pixbase + px0) * 64 + o0);
    float4 xv1 = *(const float4*)(g_xT + (pixbase + px1) * 64 + o0);
    const float* xa0 = (const float*)&xv0;
    const float* xa1 = (const float*)&xv1;
#pragma unroll
    for (int j = 0; j < 4; ++j) {
        float2 rr;
        rr.x = xa0[j] + d[0][j] + xa0[j] * gm[0][j] + bt[0][j];
        rr.y = xa1[j] + d[1][j] + xa1[j] * gm[1][j] + bt[1][j];
        *(float2*)(out + ((size_t)(b * Cn + o0 + j) * Hn + h) * Wn + w0 + px0) = rr;
    }
}

// ---------------- launch ----------------
extern "C" void kernel_launch(void* const* d_in, const int* in_sizes, int n_in,
                              void* d_out, int out_size) {
    const float* x     = (const float*)d_in[0];
    const float* inter = (const float*)d_in[1];
    const float* w_off = (const float*)d_in[2];
    const float* b_off = (const float*)d_in[3];
    const float* w_dcn = (const float*)d_in[4];
    const float* wg1   = (const float*)d_in[5];
    const float* wg2   = (const float*)d_in[6];
    const float* wb1   = (const float*)d_in[7];
    const float* wb2   = (const float*)d_in[8];
    float* out = (float*)d_out;

    const int fused_smem = (576 * 34 + 32 * 27) * 4;   // 81792 B
    static int attr_done = 0;
    if (!attr_done) {
        cudaFuncSetAttribute(fused_k, cudaFuncAttributeMaxDynamicSharedMemorySize, fused_smem);
        attr_done = 1;
    }

    prep_weights<<<144, 256>>>(w_off, w_dcn, wg1, wg2, wb1, wb2);
    transpose_k<<<dim3(HWn / 32, Cn / 32, Bn), dim3(32, 8)>>>(x, 0);
    transpose_k<<<dim3(HWn / 32, Cn / 32, Bn), dim3(32, 8)>>>(inter, 1);
    offset_conv_k<<<dim3(Wn / 64, Hn, Bn), 256>>>(x, inter, b_off);
    fused_k<<<dim3(Wn / 32, Hn, Bn), 256, fused_smem>>>(out);
}

// round 12
// speedup vs baseline: 1.3116x; 1.3116x over previous
#include <cuda_runtime.h>

#define Bn 4
#define Cn 64
#define Hn 128
#define Wn 128
#define HWn (Hn*Wn)

// ---------------- scratch (device globals; no runtime allocation) ----------------
__device__ __align__(16) float g_xT[Bn*HWn*Cn];       // x  in [B,H,W,C]
__device__ __align__(16) float g_interT[Bn*HWn*Cn];   // inter in [B,H,W,C]
__device__ __align__(16) float g_om[Bn*HWn*32];       // offsets+mask, pixel-major, pad 32
__device__ __align__(16) float g_woffT[1152*32];      // [r=cin*9+tap][o(pad32)]
__device__ __align__(16) float g_wdcnT[576*64];       // [r=c*9+k][o]
__device__ __align__(16) float g_wg1T[4096];          // [c][o]
__device__ __align__(16) float g_wg2T[4096];
__device__ __align__(16) float g_wb1T[4096];
__device__ __align__(16) float g_wb2T[4096];

// ---------------- weight prep ----------------
__global__ void prep_weights(const float* __restrict__ w_off,
                             const float* __restrict__ w_dcn,
                             const float* __restrict__ wg1, const float* __restrict__ wg2,
                             const float* __restrict__ wb1, const float* __restrict__ wb2) {
    int idx = blockIdx.x * blockDim.x + threadIdx.x;
    if (idx < 1152*32) {
        int r = idx >> 5, o = idx & 31;
        g_woffT[idx] = (o < 27) ? w_off[o*1152 + r] : 0.f;
    }
    if (idx < 576*64) {
        int r = idx >> 6, o = idx & 63;
        g_wdcnT[idx] = w_dcn[o*576 + r];
    }
    if (idx < 4096) {
        int c = idx >> 6, o = idx & 63;
        g_wg1T[idx] = wg1[o*64 + c];
        g_wg2T[idx] = wg2[o*64 + c];
        g_wb1T[idx] = wb1[o*64 + c];
        g_wb2T[idx] = wb2[o*64 + c];
    }
}

// ---------------- NCHW -> NHWC transpose ----------------
__global__ void transpose_k(const float* __restrict__ in, int which) {
    __shared__ float tile[32][33];
    float* out = which ? g_interT : g_xT;
    int b = blockIdx.z;
    int n0 = blockIdx.x * 32;
    int c0 = blockIdx.y * 32;
    int tx = threadIdx.x, ty = threadIdx.y;
    const float* src = in + (size_t)b * Cn * HWn;
    float* dst = out + (size_t)b * HWn * Cn;
#pragma unroll
    for (int i = 0; i < 32; i += 8)
        tile[ty + i][tx] = src[(size_t)(c0 + ty + i) * HWn + n0 + tx];
    __syncthreads();
#pragma unroll
    for (int i = 0; i < 32; i += 8)
        dst[(size_t)(n0 + ty + i) * Cn + c0 + tx] = tile[tx][ty + i];
}

// ---------------- offset conv ----------------
// block: 128 thr covering 64 px x 32 outputs.
// tid: og = tid>>4 (8 groups of 4 outputs), quad = tid&15 -> pixels quad*4..quad*4+3.
// warp = 2 adjacent og halves (weights 32B-contiguous -> 1 wavefront) x 16 px-quads
// (both halves read identical patch addresses -> broadcast dedup).
// smem: 32ch x 3rows x 68cols (pitch 68 keeps float4 patch loads 16B-aligned).
__global__ __launch_bounds__(128) void offset_conv_k(
    const float* __restrict__ x, const float* __restrict__ inter,
    const float* __restrict__ b_off) {
    __shared__ __align__(16) float s_in[32 * 204];   // [ci][ry(3)][cx(68)] = 26112 B
    int b = blockIdx.z, h = blockIdx.y, w0 = blockIdx.x * 64;
    int tid = threadIdx.x;
    int og = tid >> 4, quad = tid & 15;
    int o0 = og * 4, p0 = quad * 4;
    float acc[4][4] = {{0.f}};   // [px][out]

    for (int half = 0; half < 2; ++half) {
        const float* src = half ? inter : x;
        for (int chunk = 0; chunk < 2; ++chunk) {
            int cbase = chunk * 32;
            __syncthreads();
            for (int idx = tid; idx < 32 * 204; idx += 128) {
                int ci = idx / 204; int rem = idx - ci * 204;
                int ry = rem / 68;  int cx = rem - ry * 68;
                int y = h - 1 + ry, xw = w0 - 1 + cx;
                float v = 0.f;
                if (cx < 66 && (unsigned)y < (unsigned)Hn && (unsigned)xw < (unsigned)Wn)
                    v = src[((size_t)(b * Cn + cbase + ci) * Hn + y) * Wn + xw];
                s_in[idx] = v;
            }
            __syncthreads();
            const float* wb = g_woffT + (half * 64 + cbase) * 288 + o0;
            for (int ci = 0; ci < 32; ++ci) {
                const float* srow = s_in + ci * 204 + p0;
                // 3x6 input patch for this thread's 4 pixels
                float v[3][6];
#pragma unroll
                for (int ry = 0; ry < 3; ++ry) {
                    float4 u0 = *(const float4*)(srow + ry * 68);
                    float2 u1 = *(const float2*)(srow + ry * 68 + 4);
                    v[ry][0] = u0.x; v[ry][1] = u0.y; v[ry][2] = u0.z; v[ry][3] = u0.w;
                    v[ry][4] = u1.x; v[ry][5] = u1.y;
                }
                const float* wr = wb + ci * 288;
#pragma unroll
                for (int tap = 0; tap < 9; ++tap) {
                    float4 w4 = *(const float4*)(wr + tap * 32);
                    int ry = tap / 3, kx = tap - ry * 3;
#pragma unroll
                    for (int px = 0; px < 4; ++px) {
                        float s = v[ry][kx + px];
                        acc[px][0] += w4.x * s; acc[px][1] += w4.y * s;
                        acc[px][2] += w4.z * s; acc[px][3] += w4.w * s;
                    }
                }
            }
        }
    }

    float bj[4];
#pragma unroll
    for (int j = 0; j < 4; ++j) bj[j] = (o0 + j < 27) ? b_off[o0 + j] : 0.f;

    size_t pixbase = ((size_t)b * Hn + h) * Wn + w0;
#pragma unroll
    for (int px = 0; px < 4; ++px) {
        float4 r;
        float* rv = (float*)&r;
#pragma unroll
        for (int j = 0; j < 4; ++j) {
            int o = o0 + j;
            float vv = acc[px][j] + bj[j];
            if (o >= 18 && o < 27) vv = 1.f / (1.f + expf(-vv));
            rv[j] = vv;
        }
        *(float4*)(g_om + (pixbase + p0 + px) * 32 + o0) = r;
    }
}

__device__ __forceinline__ float lrelu(float v) { return v >= 0.f ? v : 0.1f * v; }

// ---------------- fused: gamma/beta chains + deformable sampling + DCN + residual ----
// (reverted to the R9 configuration: 16 px/block, pitch-17 samples, 41KB static smem)
// block: 256 thr = 16 o-groups(4 out) x 16 pixels
__global__ __launch_bounds__(256) void fused_k(float* __restrict__ out) {
    __shared__ __align__(16) float s_samp[576 * 17]; // [r=c*9+k][p], pad 17 -> conflict-free
    __shared__ float s_om[16 * 27];
    // aliased into s_samp (dead before sampling phase writes it):
    float* s_iv = s_samp;                  // [16][65]
    float* s_t1 = s_samp + 1040;           // [16][66]
    float* s_t2 = s_samp + 1040 + 1056;    // [16][66]

    int b = blockIdx.z, h = blockIdx.y, w0 = blockIdx.x * 16;
    int tid = threadIdx.x;
    int og = tid >> 4, p = tid & 15, o0 = og * 4;
    size_t pixbase = ((size_t)b * Hn + h) * Wn + w0;

    for (int idx = tid; idx < 16 * 27; idx += 256) {
        int pp = idx / 27, c = idx - pp * 27;
        s_om[idx] = g_om[(pixbase + pp) * 32 + c];
    }
    for (int idx = tid; idx < 16 * 64; idx += 256) {
        int pp = idx >> 6, c = idx & 63;
        s_iv[pp * 65 + c] = g_interT[(pixbase + pp) * 64 + c];
    }
    __syncthreads();

    // stage 1: t1 = lrelu(w_g1 @ iv), t2 = lrelu(w_b1 @ iv)
    float a10 = 0, a11 = 0, a12 = 0, a13 = 0;
    float a20 = 0, a21 = 0, a22 = 0, a23 = 0;
#pragma unroll 4
    for (int c = 0; c < 64; ++c) {
        float v = s_iv[p * 65 + c];
        float4 w1 = *(const float4*)(g_wg1T + c * 64 + o0);
        float4 w2 = *(const float4*)(g_wb1T + c * 64 + o0);
        a10 += w1.x * v; a11 += w1.y * v; a12 += w1.z * v; a13 += w1.w * v;
        a20 += w2.x * v; a21 += w2.y * v; a22 += w2.z * v; a23 += w2.w * v;
    }
    {
        // scalar stores: p*66+o0 not 16B-aligned for odd p; stride 66 keeps
        // stage-2 reads bank-conflict-free.
        float* t1p = s_t1 + p * 66 + o0;
        float* t2p = s_t2 + p * 66 + o0;
        t1p[0] = lrelu(a10); t1p[1] = lrelu(a11); t1p[2] = lrelu(a12); t1p[3] = lrelu(a13);
        t2p[0] = lrelu(a20); t2p[1] = lrelu(a21); t2p[2] = lrelu(a22); t2p[3] = lrelu(a23);
    }
    __syncthreads();

    // stage 2: gamma = w_g2 @ t1, beta = w_b2 @ t2 (kept in regs)
    float g0 = 0, g1 = 0, g2 = 0, g3 = 0;
    float e0 = 0, e1 = 0, e2 = 0, e3 = 0;
#pragma unroll 4
    for (int c = 0; c < 64; ++c) {
        float v1 = s_t1[p * 66 + c];
        float v2 = s_t2[p * 66 + c];
        float4 w1 = *(const float4*)(g_wg2T + c * 64 + o0);
        float4 w2 = *(const float4*)(g_wb2T + c * 64 + o0);
        g0 += w1.x * v1; g1 += w1.y * v1; g2 += w1.z * v1; g3 += w1.w * v1;
        e0 += w2.x * v2; e1 += w2.y * v2; e2 += w2.z * v2; e3 += w2.w * v2;
    }
    __syncthreads();   // aliased region reads done before sampling overwrites

    // sampling: s_samp[(c*9+k)*17 + p] = bilinear(x, p, k) * mask
    int wi = tid >> 5, lane = tid & 31;
    for (int task = wi; task < 144; task += 8) {
        int pp = task / 9, k = task - pp * 9;
        float dy = s_om[pp * 27 + k];
        float dx = s_om[pp * 27 + 9 + k];
        float m  = s_om[pp * 27 + 18 + k];
        int ky = k / 3, kx = k - ky * 3;
        float py = (float)(h + ky - 1) + dy;
        float px = (float)(w0 + pp + kx - 1) + dx;
        float fy = floorf(py), fx = floorf(px);
        float wy = py - fy, wx = px - fx;
        int y0 = (int)fy, x0 = (int)fx;
        bool vy0 = (unsigned)y0 < (unsigned)Hn;
        bool vy1 = (unsigned)(y0 + 1) < (unsigned)Hn;
        bool vx0 = (unsigned)x0 < (unsigned)Wn;
        bool vx1 = (unsigned)(x0 + 1) < (unsigned)Wn;
        float w00 = (1.f - wy) * (1.f - wx) * m;
        float w01 = (1.f - wy) * wx * m;
        float w10 = wy * (1.f - wx) * m;
        float w11 = wy * wx * m;
        const float* xb = g_xT + (size_t)b * HWn * Cn
                          + ((long long)y0 * Wn + x0) * Cn;
#pragma unroll
        for (int cc = 0; cc < 2; ++cc) {
            int c = lane + cc * 32;
            float v00 = (vy0 && vx0) ? xb[c] : 0.f;
            float v01 = (vy0 && vx1) ? xb[c + Cn] : 0.f;
            float v10 = (vy1 && vx0) ? xb[c + Wn * Cn] : 0.f;
            float v11 = (vy1 && vx1) ? xb[c + Wn * Cn + Cn] : 0.f;
            float val = v00 * w00 + v01 * w01 + v10 * w10 + v11 * w11;
            s_samp[(c * 9 + k) * 17 + pp] = val;
        }
    }
    __syncthreads();

    // DCN: d[o] = sum_r wdcnT[r][o] * samp[r][p]
    float d0 = 0, d1 = 0, d2 = 0, d3 = 0;
#pragma unroll 4
    for (int r = 0; r < 576; ++r) {
        float4 w4 = *(const float4*)(g_wdcnT + r * 64 + o0);
        float s = s_samp[r * 17 + p];
        d0 += w4.x * s; d1 += w4.y * s; d2 += w4.z * s; d3 += w4.w * s;
    }

    // epilogue: out = x + dcn + x*gamma + beta   (NCHW output)
    float4 xv = *(const float4*)(g_xT + (pixbase + p) * 64 + o0);
    float r0 = xv.x + d0 + xv.x * g0 + e0;
    float r1 = xv.y + d1 + xv.y * g1 + e1;
    float r2 = xv.z + d2 + xv.z * g2 + e2;
    float r3 = xv.w + d3 + xv.w * g3 + e3;
    size_t obase = ((size_t)(b * Cn + o0) * Hn + h) * Wn + w0 + p;
    out[obase]            = r0;
    out[obase + HWn]      = r1;
    out[obase + 2 * HWn]  = r2;
    out[obase + 3 * HWn]  = r3;
}

// ---------------- launch ----------------
extern "C" void kernel_launch(void* const* d_in, const int* in_sizes, int n_in,
                              void* d_out, int out_size) {
    const float* x     = (const float*)d_in[0];
    const float* inter = (const float*)d_in[1];
    const float* w_off = (const float*)d_in[2];
    const float* b_off = (const float*)d_in[3];
    const float* w_dcn = (const float*)d_in[4];
    const float* wg1   = (const float*)d_in[5];
    const float* wg2   = (const float*)d_in[6];
    const float* wb1   = (const float*)d_in[7];
    const float* wb2   = (const float*)d_in[8];
    float* out = (float*)d_out;

    prep_weights<<<144, 256>>>(w_off, w_dcn, wg1, wg2, wb1, wb2);
    transpose_k<<<dim3(HWn / 32, Cn / 32, Bn), dim3(32, 8)>>>(x, 0);
    transpose_k<<<dim3(HWn / 32, Cn / 32, Bn), dim3(32, 8)>>>(inter, 1);
    offset_conv_k<<<dim3(Wn / 64, Hn, Bn), 128>>>(x, inter, b_off);
    fused_k<<<dim3(Wn / 16, Hn, Bn), 256>>>(out);
}

// round 13
// speedup vs baseline: 1.5898x; 1.2121x over previous
#include <cuda_runtime.h>

#define Bn 4
#define Cn 64
#define Hn 128
#define Wn 128
#define HWn (Hn*Wn)

// ---------------- scratch (device globals; no runtime allocation) ----------------
__device__ __align__(16) float g_xT[Bn*HWn*Cn];       // x  in [B,H,W,C]
__device__ __align__(16) float g_interT[Bn*HWn*Cn];   // inter in [B,H,W,C]
__device__ __align__(16) float g_om[Bn*HWn*32];       // offsets+mask, pixel-major, pad 32
__device__ __align__(16) float g_woffT[1152*32];      // [r=cin*9+tap][o(pad32)]
__device__ __align__(16) float g_wdcnT[576*64];       // [r=c*9+k][o]
__device__ __align__(16) float g_wg1T[4096];          // [c][o]
__device__ __align__(16) float g_wg2T[4096];
__device__ __align__(16) float g_wb1T[4096];
__device__ __align__(16) float g_wb2T[4096];

// ---------------- weight prep ----------------
__global__ void prep_weights(const float* __restrict__ w_off,
                             const float* __restrict__ w_dcn,
                             const float* __restrict__ wg1, const float* __restrict__ wg2,
                             const float* __restrict__ wb1, const float* __restrict__ wb2) {
    int idx = blockIdx.x * blockDim.x + threadIdx.x;
    if (idx < 1152*32) {
        int r = idx >> 5, o = idx & 31;
        g_woffT[idx] = (o < 27) ? w_off[o*1152 + r] : 0.f;
    }
    if (idx < 576*64) {
        int r = idx >> 6, o = idx & 63;
        g_wdcnT[idx] = w_dcn[o*576 + r];
    }
    if (idx < 4096) {
        int c = idx >> 6, o = idx & 63;
        g_wg1T[idx] = wg1[o*64 + c];
        g_wg2T[idx] = wg2[o*64 + c];
        g_wb1T[idx] = wb1[o*64 + c];
        g_wb2T[idx] = wb2[o*64 + c];
    }
}

// ---------------- NCHW -> NHWC transpose (x and inter in one launch, z = 2*Bn) ----
__global__ void transpose_k(const float* __restrict__ in_x, const float* __restrict__ in_i) {
    __shared__ float tile[32][33];
    int z = blockIdx.z;             // 0..7: low 2 bits batch, bit2 selects tensor
    int b = z & 3;
    const float* in = (z & 4) ? in_i : in_x;
    float* out = (z & 4) ? g_interT : g_xT;
    int n0 = blockIdx.x * 32;
    int c0 = blockIdx.y * 32;
    int tx = threadIdx.x, ty = threadIdx.y;
    const float* src = in + (size_t)b * Cn * HWn;
    float* dst = out + (size_t)b * HWn * Cn;
#pragma unroll
    for (int i = 0; i < 32; i += 8)
        tile[ty + i][tx] = src[(size_t)(c0 + ty + i) * HWn + n0 + tx];
    __syncthreads();
#pragma unroll
    for (int i = 0; i < 32; i += 8)
        dst[(size_t)(n0 + ty + i) * Cn + c0 + tx] = tile[tx][ty + i];
}

// ---------------- offset conv (unchanged from R12 — near its floor) ----------------
__global__ __launch_bounds__(128) void offset_conv_k(
    const float* __restrict__ x, const float* __restrict__ inter,
    const float* __restrict__ b_off) {
    __shared__ __align__(16) float s_in[32 * 204];   // [ci][ry(3)][cx(68)] = 26112 B
    int b = blockIdx.z, h = blockIdx.y, w0 = blockIdx.x * 64;
    int tid = threadIdx.x;
    int og = tid >> 4, quad = tid & 15;
    int o0 = og * 4, p0 = quad * 4;
    float acc[4][4] = {{0.f}};   // [px][out]

    for (int half = 0; half < 2; ++half) {
        const float* src = half ? inter : x;
        for (int chunk = 0; chunk < 2; ++chunk) {
            int cbase = chunk * 32;
            __syncthreads();
            for (int idx = tid; idx < 32 * 204; idx += 128) {
                int ci = idx / 204; int rem = idx - ci * 204;
                int ry = rem / 68;  int cx = rem - ry * 68;
                int y = h - 1 + ry, xw = w0 - 1 + cx;
                float v = 0.f;
                if (cx < 66 && (unsigned)y < (unsigned)Hn && (unsigned)xw < (unsigned)Wn)
                    v = src[((size_t)(b * Cn + cbase + ci) * Hn + y) * Wn + xw];
                s_in[idx] = v;
            }
            __syncthreads();
            const float* wb = g_woffT + (half * 64 + cbase) * 288 + o0;
            for (int ci = 0; ci < 32; ++ci) {
                const float* srow = s_in + ci * 204 + p0;
                float v[3][6];
#pragma unroll
                for (int ry = 0; ry < 3; ++ry) {
                    float4 u0 = *(const float4*)(srow + ry * 68);
                    float2 u1 = *(const float2*)(srow + ry * 68 + 4);
                    v[ry][0] = u0.x; v[ry][1] = u0.y; v[ry][2] = u0.z; v[ry][3] = u0.w;
                    v[ry][4] = u1.x; v[ry][5] = u1.y;
                }
                const float* wr = wb + ci * 288;
#pragma unroll
                for (int tap = 0; tap < 9; ++tap) {
                    float4 w4 = *(const float4*)(wr + tap * 32);
                    int ry = tap / 3, kx = tap - ry * 3;
#pragma unroll
                    for (int px = 0; px < 4; ++px) {
                        float s = v[ry][kx + px];
                        acc[px][0] += w4.x * s; acc[px][1] += w4.y * s;
                        acc[px][2] += w4.z * s; acc[px][3] += w4.w * s;
                    }
                }
            }
        }
    }

    float bj[4];
#pragma unroll
    for (int j = 0; j < 4; ++j) bj[j] = (o0 + j < 27) ? b_off[o0 + j] : 0.f;

    size_t pixbase = ((size_t)b * Hn + h) * Wn + w0;
#pragma unroll
    for (int px = 0; px < 4; ++px) {
        float4 r;
        float* rv = (float*)&r;
#pragma unroll
        for (int j = 0; j < 4; ++j) {
            int o = o0 + j;
            float vv = acc[px][j] + bj[j];
            if (o >= 18 && o < 27) vv = 1.f / (1.f + expf(-vv));
            rv[j] = vv;
        }
        *(float4*)(g_om + (pixbase + p0 + px) * 32 + o0) = r;
    }
}

__device__ __forceinline__ float lrelu(float v) { return v >= 0.f ? v : 0.1f * v; }

// ---------------- fused: SFT chains + deformable sampling + DCN + residual ----
// 128 thr covering 16 px x 64 out: og = tid>>3 (16 groups of 4 outputs),
// t = tid&7 -> pixel pair (2t, 2t+1). Warp = 4 og x 8 t.
// s_samp pitch 18: LDS.64 (18r+2t) is 8B-aligned for all r; STS 2-way conflict only.
// smem: 576*18 + 16*27 floats = 43200 B static -> 5 blocks/SM.
__global__ __launch_bounds__(128) void fused_k(float* __restrict__ out) {
    __shared__ __align__(16) float s_samp[576 * 18]; // [r=c*9+k][p(pad18)]
    __shared__ float s_om[16 * 27];
    // aliased into s_samp (dead before sampling phase writes it):
    float* s_iv = s_samp;                  // [16][65]
    float* s_t1 = s_samp + 1040;           // [16][66]
    float* s_t2 = s_samp + 1040 + 1056;    // [16][66]

    int b = blockIdx.z, h = blockIdx.y, w0 = blockIdx.x * 16;
    int tid = threadIdx.x;
    int og = tid >> 3, t = tid & 7, o0 = og * 4;
    int px0 = 2 * t, px1 = 2 * t + 1;
    size_t pixbase = ((size_t)b * Hn + h) * Wn + w0;

    for (int idx = tid; idx < 16 * 27; idx += 128) {
        int pp = idx / 27, c = idx - pp * 27;
        s_om[idx] = g_om[(pixbase + pp) * 32 + c];
    }
    for (int idx = tid; idx < 16 * 64; idx += 128) {
        int pp = idx >> 6, c = idx & 63;
        s_iv[pp * 65 + c] = g_interT[(pixbase + pp) * 64 + c];
    }
    __syncthreads();

    // stage 1: t1 = lrelu(w_g1 @ iv), t2 = lrelu(w_b1 @ iv)   (2 px/thread)
    float a1[2][4] = {{0}}, a2[2][4] = {{0}};
#pragma unroll 4
    for (int c = 0; c < 64; ++c) {
        float v0 = s_iv[px0 * 65 + c];
        float v1 = s_iv[px1 * 65 + c];
        float4 w1 = *(const float4*)(g_wg1T + c * 64 + o0);
        float4 w2 = *(const float4*)(g_wb1T + c * 64 + o0);
        a1[0][0] += w1.x * v0; a1[0][1] += w1.y * v0; a1[0][2] += w1.z * v0; a1[0][3] += w1.w * v0;
        a1[1][0] += w1.x * v1; a1[1][1] += w1.y * v1; a1[1][2] += w1.z * v1; a1[1][3] += w1.w * v1;
        a2[0][0] += w2.x * v0; a2[0][1] += w2.y * v0; a2[0][2] += w2.z * v0; a2[0][3] += w2.w * v0;
        a2[1][0] += w2.x * v1; a2[1][1] += w2.y * v1; a2[1][2] += w2.z * v1; a2[1][3] += w2.w * v1;
    }
#pragma unroll
    for (int px = 0; px < 2; ++px) {
        float* t1p = s_t1 + (px0 + px) * 66 + o0;   // scalar: p*66+o0 not 16B-aligned
        float* t2p = s_t2 + (px0 + px) * 66 + o0;
#pragma unroll
        for (int j = 0; j < 4; ++j) { t1p[j] = lrelu(a1[px][j]); t2p[j] = lrelu(a2[px][j]); }
    }
    __syncthreads();

    // stage 2: gamma = w_g2 @ t1, beta = w_b2 @ t2 (kept in regs)
    float gm[2][4] = {{0}}, bt[2][4] = {{0}};
#pragma unroll 4
    for (int c = 0; c < 64; ++c) {
        float u0 = s_t1[px0 * 66 + c];
        float u1 = s_t1[px1 * 66 + c];
        float v0 = s_t2[px0 * 66 + c];
        float v1 = s_t2[px1 * 66 + c];
        float4 w1 = *(const float4*)(g_wg2T + c * 64 + o0);
        float4 w2 = *(const float4*)(g_wb2T + c * 64 + o0);
        gm[0][0] += w1.x * u0; gm[0][1] += w1.y * u0; gm[0][2] += w1.z * u0; gm[0][3] += w1.w * u0;
        gm[1][0] += w1.x * u1; gm[1][1] += w1.y * u1; gm[1][2] += w1.z * u1; gm[1][3] += w1.w * u1;
        bt[0][0] += w2.x * v0; bt[0][1] += w2.y * v0; bt[0][2] += w2.z * v0; bt[0][3] += w2.w * v0;
        bt[1][0] += w2.x * v1; bt[1][1] += w2.y * v1; bt[1][2] += w2.z * v1; bt[1][3] += w2.w * v1;
    }
    __syncthreads();   // aliased region reads done before sampling overwrites

    // sampling: s_samp[(c*9+k)*18 + pp] = bilinear(x, pp, k) * mask   (4 warps)
    int wi = tid >> 5, lane = tid & 31;
    for (int task = wi; task < 144; task += 4) {
        int pp = task / 9, k = task - pp * 9;
        float dy = s_om[pp * 27 + k];
        float dx = s_om[pp * 27 + 9 + k];
        float m  = s_om[pp * 27 + 18 + k];
        int ky = k / 3, kx = k - ky * 3;
        float py = (float)(h + ky - 1) + dy;
        float px = (float)(w0 + pp + kx - 1) + dx;
        float fy = floorf(py), fx = floorf(px);
        float wy = py - fy, wx = px - fx;
        int y0 = (int)fy, x0 = (int)fx;
        bool vy0 = (unsigned)y0 < (unsigned)Hn;
        bool vy1 = (unsigned)(y0 + 1) < (unsigned)Hn;
        bool vx0 = (unsigned)x0 < (unsigned)Wn;
        bool vx1 = (unsigned)(x0 + 1) < (unsigned)Wn;
        float w00 = (1.f - wy) * (1.f - wx) * m;
        float w01 = (1.f - wy) * wx * m;
        float w10 = wy * (1.f - wx) * m;
        float w11 = wy * wx * m;
        const float* xb = g_xT + (size_t)b * HWn * Cn
                          + ((long long)y0 * Wn + x0) * Cn;
#pragma unroll
        for (int cc = 0; cc < 2; ++cc) {
            int c = lane + cc * 32;
            float v00 = (vy0 && vx0) ? xb[c] : 0.f;
            float v01 = (vy0 && vx1) ? xb[c + Cn] : 0.f;
            float v10 = (vy1 && vx0) ? xb[c + Wn * Cn] : 0.f;
            float v11 = (vy1 && vx1) ? xb[c + Wn * Cn + Cn] : 0.f;
            float val = v00 * w00 + v01 * w01 + v10 * w10 + v11 * w11;
            s_samp[(c * 9 + k) * 18 + pp] = val;
        }
    }
    __syncthreads();

    // DCN: d[px][o] = sum_r wdcnT[r][o] * samp[r][px]   (LDS.64 pixel pair, 8 FFMA)
    float d[2][4] = {{0}};
#pragma unroll 4
    for (int r = 0; r < 576; ++r) {
        float4 w4 = *(const float4*)(g_wdcnT + r * 64 + o0);
        float2 sp = *(const float2*)(s_samp + r * 18 + px0);
        d[0][0] += w4.x * sp.x; d[0][1] += w4.y * sp.x; d[0][2] += w4.z * sp.x; d[0][3] += w4.w * sp.x;
        d[1][0] += w4.x * sp.y; d[1][1] += w4.y * sp.y; d[1][2] += w4.z * sp.y; d[1][3] += w4.w * sp.y;
    }

    // epilogue: out = x + dcn + x*gamma + beta   (NCHW, float2 across pixel pair)
    float4 xv0 = *(const float4*)(g_xT + (pixbase + px0) * 64 + o0);
    float4 xv1 = *(const float4*)(g_xT + (pixbase + px1) * 64 + o0);
    const float* xa0 = (const float*)&xv0;
    const float* xa1 = (const float*)&xv1;
#pragma unroll
    for (int j = 0; j < 4; ++j) {
        float2 rr;
        rr.x = xa0[j] + d[0][j] + xa0[j] * gm[0][j] + bt[0][j];
        rr.y = xa1[j] + d[1][j] + xa1[j] * gm[1][j] + bt[1][j];
        *(float2*)(out + ((size_t)(b * Cn + o0 + j) * Hn + h) * Wn + w0 + px0) = rr;
    }
}

// ---------------- launch ----------------
extern "C" void kernel_launch(void* const* d_in, const int* in_sizes, int n_in,
                              void* d_out, int out_size) {
    const float* x     = (const float*)d_in[0];
    const float* inter = (const float*)d_in[1];
    const float* w_off = (const float*)d_in[2];
    const float* b_off = (const float*)d_in[3];
    const float* w_dcn = (const float*)d_in[4];
    const float* wg1   = (const float*)d_in[5];
    const float* wg2   = (const float*)d_in[6];
    const float* wb1   = (const float*)d_in[7];
    const float* wb2   = (const float*)d_in[8];
    float* out = (float*)d_out;

    prep_weights<<<144, 256>>>(w_off, w_dcn, wg1, wg2, wb1, wb2);
    transpose_k<<<dim3(HWn / 32, Cn / 32, 2 * Bn), dim3(32, 8)>>>(x, inter);
    offset_conv_k<<<dim3(Wn / 64, Hn, Bn), 128>>>(x, inter, b_off);
    fused_k<<<dim3(Wn / 16, Hn, Bn), 128>>>(out);
}

// round 14
// speedup vs baseline: 1.7034x; 1.0714x over previous
#include <cuda_runtime.h>
#include <cuda_fp16.h>

#define Bn 4
#define Cn 64
#define Hn 128
#define Wn 128
#define HWn (Hn*Wn)

typedef unsigned long long u64;

// packed f32x2 helpers (sm_103a): 2 fp32 MACs per instruction, RN rounding
__device__ __forceinline__ u64 pk2(float a, float b) {
    u64 r; asm("mov.b64 %0, {%1, %2};" : "=l"(r) : "f"(a), "f"(b)); return r;
}
__device__ __forceinline__ void fma2(u64& d, u64 a, u64 b) {
    asm("fma.rn.f32x2 %0, %1, %2, %0;" : "+l"(d) : "l"(a), "l"(b));
}
__device__ __forceinline__ float2 up2(u64 v) {
    float2 r; asm("mov.b64 {%0, %1}, %2;" : "=f"(r.x), "=f"(r.y) : "l"(v)); return r;
}

// ---------------- scratch ----------------
__device__ __align__(16) float g_xT[Bn*HWn*Cn];       // x  in [B,H,W,C]
__device__ __align__(16) float g_interT[Bn*HWn*Cn];   // inter in [B,H,W,C]
__device__ __align__(16) float g_om[Bn*HWn*32];       // offsets+mask, pixel-major, pad 32
__device__ __align__(16) float g_woffT[1152*32];      // [r=cin*9+tap][o(pad32)]
__device__ __align__(16) float g_wdcnT[576*64];       // [r=c*9+k][o]
__device__ __align__(16) float g_wg1T[4096];          // [c][o]
__device__ __align__(16) float g_wg2T[4096];
__device__ __align__(16) float g_wb1T[4096];
__device__ __align__(16) float g_wb2T[4096];

// ---------------- weight prep ----------------
__global__ void prep_weights(const float* __restrict__ w_off,
                             const float* __restrict__ w_dcn,
                             const float* __restrict__ wg1, const float* __restrict__ wg2,
                             const float* __restrict__ wb1, const float* __restrict__ wb2) {
    int idx = blockIdx.x * blockDim.x + threadIdx.x;
    if (idx < 1152*32) {
        int r = idx >> 5, o = idx & 31;
        g_woffT[idx] = (o < 27) ? w_off[o*1152 + r] : 0.f;
    }
    if (idx < 576*64) {
        int r = idx >> 6, o = idx & 63;
        g_wdcnT[idx] = w_dcn[o*576 + r];
    }
    if (idx < 4096) {
        int c = idx >> 6, o = idx & 63;
        g_wg1T[idx] = wg1[o*64 + c];
        g_wg2T[idx] = wg2[o*64 + c];
        g_wb1T[idx] = wb1[o*64 + c];
        g_wb2T[idx] = wb2[o*64 + c];
    }
}

// ---------------- NCHW -> NHWC transpose (x + inter in one launch) ----------------
__global__ void transpose_k(const float* __restrict__ in_x, const float* __restrict__ in_i) {
    __shared__ float tile[32][33];
    int z = blockIdx.z;
    int b = z & 3;
    const float* in = (z & 4) ? in_i : in_x;
    float* out = (z & 4) ? g_interT : g_xT;
    int n0 = blockIdx.x * 32;
    int c0 = blockIdx.y * 32;
    int tx = threadIdx.x, ty = threadIdx.y;
    const float* src = in + (size_t)b * Cn * HWn;
    float* dst = out + (size_t)b * HWn * Cn;
#pragma unroll
    for (int i = 0; i < 32; i += 8)
        tile[ty + i][tx] = src[(size_t)(c0 + ty + i) * HWn + n0 + tx];
    __syncthreads();
#pragma unroll
    for (int i = 0; i < 32; i += 8)
        dst[(size_t)(n0 + ty + i) * Cn + c0 + tx] = tile[tx][ty + i];
}

// ---------------- offset conv ----------------
// 128 thr: og = tid&7 (8 groups x 4 out), quad = tid>>3 (16 quads x 4 px) -> 64 px.
// Warp = all 8 og x 4 quads: weight LDG.128 = one 128B line/warp; patch LDS broadcast.
// FFMA2: acc pairs over outputs; sample packed (s,s) per row, reused across taps.
__global__ __launch_bounds__(128) void offset_conv_k(
    const float* __restrict__ x, const float* __restrict__ inter,
    const float* __restrict__ b_off) {
    __shared__ __align__(16) float s_in[32 * 204];   // [ci][ry(3)][cx(68)] = 26112 B
    int b = blockIdx.z, h = blockIdx.y, w0 = blockIdx.x * 64;
    int tid = threadIdx.x;
    int og = tid & 7, quad = tid >> 3;
    int o0 = og * 4, p0 = quad * 4;
    u64 acc[4][2] = {{0,0},{0,0},{0,0},{0,0}};   // [px][out-pair]

    for (int half = 0; half < 2; ++half) {
        const float* src = half ? inter : x;
        for (int chunk = 0; chunk < 2; ++chunk) {
            int cbase = chunk * 32;
            __syncthreads();
            for (int idx = tid; idx < 32 * 204; idx += 128) {
                int ci = idx / 204; int rem = idx - ci * 204;
                int ry = rem / 68;  int cx = rem - ry * 68;
                int y = h - 1 + ry, xw = w0 - 1 + cx;
                float v = 0.f;
                if (cx < 66 && (unsigned)y < (unsigned)Hn && (unsigned)xw < (unsigned)Wn)
                    v = src[((size_t)(b * Cn + cbase + ci) * Hn + y) * Wn + xw];
                s_in[idx] = v;
            }
            __syncthreads();
            const float* wb = g_woffT + (half * 64 + cbase) * 288 + o0;
            for (int ci = 0; ci < 32; ++ci) {
                const float* srow = s_in + ci * 204 + p0;
                const float* wr = wb + ci * 288;
#pragma unroll
                for (int ry = 0; ry < 3; ++ry) {
                    float4 u0 = *(const float4*)(srow + ry * 68);
                    float2 u1 = *(const float2*)(srow + ry * 68 + 4);
                    u64 vp[6];
                    vp[0] = pk2(u0.x, u0.x); vp[1] = pk2(u0.y, u0.y);
                    vp[2] = pk2(u0.z, u0.z); vp[3] = pk2(u0.w, u0.w);
                    vp[4] = pk2(u1.x, u1.x); vp[5] = pk2(u1.y, u1.y);
#pragma unroll
                    for (int kx = 0; kx < 3; ++kx) {
                        ulonglong2 wp = *(const ulonglong2*)(wr + (ry * 3 + kx) * 32);
#pragma unroll
                        for (int px = 0; px < 4; ++px) {
                            fma2(acc[px][0], wp.x, vp[kx + px]);
                            fma2(acc[px][1], wp.y, vp[kx + px]);
                        }
                    }
                }
            }
        }
    }

    float bj[4];
#pragma unroll
    for (int j = 0; j < 4; ++j) bj[j] = (o0 + j < 27) ? b_off[o0 + j] : 0.f;

    size_t pixbase = ((size_t)b * Hn + h) * Wn + w0;
#pragma unroll
    for (int px = 0; px < 4; ++px) {
        float2 q0 = up2(acc[px][0]);
        float2 q1 = up2(acc[px][1]);
        float vals[4] = {q0.x, q0.y, q1.x, q1.y};
        float4 r;
        float* rv = (float*)&r;
#pragma unroll
        for (int j = 0; j < 4; ++j) {
            int o = o0 + j;
            float vv = vals[j] + bj[j];
            if (o >= 18 && o < 27) vv = 1.f / (1.f + expf(-vv));
            rv[j] = vv;
        }
        *(float4*)(g_om + (pixbase + p0 + px) * 32 + o0) = r;
    }
}

__device__ __forceinline__ float lrelu(float v) { return v >= 0.f ? v : 0.1f * v; }

// ---------------- fused: SFT chains + deformable sampling + DCN + residual ----
// 128 thr covering 16 px x 64 out: og = tid&15 (16 groups x 4 out), t = tid>>4
// -> pixel pair (2t, 2t+1). Warp = 16 og x 2 t: weight LDG = 256B contiguous (2 wf),
// sample LDS = 2-address broadcast (1 wf). Samples stored fp16 (smem 22.5 KB).
__global__ __launch_bounds__(128, 6) void fused_k(float* __restrict__ out) {
    __shared__ __align__(16) __half s_samph[576 * 18]; // [r][p(pad18)] fp16 = 20736 B
    __shared__ float s_om[16 * 27];
    // fp32 aliases into s_samph region (dead before sampling writes it): 12608 B used
    float* s_alias = reinterpret_cast<float*>(s_samph);
    float* s_iv = s_alias;                  // [16][65]
    float* s_t1 = s_alias + 1040;           // [16][66]
    float* s_t2 = s_alias + 1040 + 1056;    // [16][66]

    int b = blockIdx.z, h = blockIdx.y, w0 = blockIdx.x * 16;
    int tid = threadIdx.x;
    int og = tid & 15, t = tid >> 4, o0 = og * 4;
    int px0 = 2 * t, px1 = 2 * t + 1;
    size_t pixbase = ((size_t)b * Hn + h) * Wn + w0;

    for (int idx = tid; idx < 16 * 27; idx += 128) {
        int pp = idx / 27, c = idx - pp * 27;
        s_om[idx] = g_om[(pixbase + pp) * 32 + c];
    }
    for (int idx = tid; idx < 16 * 64; idx += 128) {
        int pp = idx >> 6, c = idx & 63;
        s_iv[pp * 65 + c] = g_interT[(pixbase + pp) * 64 + c];
    }
    __syncthreads();

    // stage 1: t1 = lrelu(w_g1 @ iv), t2 = lrelu(w_b1 @ iv)   (FFMA2, 2 px/thread)
    u64 a1p[2][2] = {{0,0},{0,0}}, a2p[2][2] = {{0,0},{0,0}};
#pragma unroll 4
    for (int c = 0; c < 64; ++c) {
        u64 v0 = pk2(s_iv[px0 * 65 + c], s_iv[px0 * 65 + c]);
        u64 v1 = pk2(s_iv[px1 * 65 + c], s_iv[px1 * 65 + c]);
        ulonglong2 w1 = *(const ulonglong2*)(g_wg1T + c * 64 + o0);
        ulonglong2 w2 = *(const ulonglong2*)(g_wb1T + c * 64 + o0);
        fma2(a1p[0][0], w1.x, v0); fma2(a1p[0][1], w1.y, v0);
        fma2(a1p[1][0], w1.x, v1); fma2(a1p[1][1], w1.y, v1);
        fma2(a2p[0][0], w2.x, v0); fma2(a2p[0][1], w2.y, v0);
        fma2(a2p[1][0], w2.x, v1); fma2(a2p[1][1], w2.y, v1);
    }
#pragma unroll
    for (int px = 0; px < 2; ++px) {
        float2 q0 = up2(a1p[px][0]), q1 = up2(a1p[px][1]);
        float2 r0 = up2(a2p[px][0]), r1 = up2(a2p[px][1]);
        float* t1p = s_t1 + (px0 + px) * 66 + o0;   // scalar stores (odd-pixel alignment)
        float* t2p = s_t2 + (px0 + px) * 66 + o0;
        t1p[0] = lrelu(q0.x); t1p[1] = lrelu(q0.y); t1p[2] = lrelu(q1.x); t1p[3] = lrelu(q1.y);
        t2p[0] = lrelu(r0.x); t2p[1] = lrelu(r0.y); t2p[2] = lrelu(r1.x); t2p[3] = lrelu(r1.y);
    }
    __syncthreads();

    // stage 2: gamma = w_g2 @ t1, beta = w_b2 @ t2 (packed accumulators kept in regs)
    u64 gmp[2][2] = {{0,0},{0,0}}, btp[2][2] = {{0,0},{0,0}};
#pragma unroll 4
    for (int c = 0; c < 64; ++c) {
        u64 u0 = pk2(s_t1[px0 * 66 + c], s_t1[px0 * 66 + c]);
        u64 u1 = pk2(s_t1[px1 * 66 + c], s_t1[px1 * 66 + c]);
        u64 v0 = pk2(s_t2[px0 * 66 + c], s_t2[px0 * 66 + c]);
        u64 v1 = pk2(s_t2[px1 * 66 + c], s_t2[px1 * 66 + c]);
        ulonglong2 w1 = *(const ulonglong2*)(g_wg2T + c * 64 + o0);
        ulonglong2 w2 = *(const ulonglong2*)(g_wb2T + c * 64 + o0);
        fma2(gmp[0][0], w1.x, u0); fma2(gmp[0][1], w1.y, u0);
        fma2(gmp[1][0], w1.x, u1); fma2(gmp[1][1], w1.y, u1);
        fma2(btp[0][0], w2.x, v0); fma2(btp[0][1], w2.y, v0);
        fma2(btp[1][0], w2.x, v1); fma2(btp[1][1], w2.y, v1);
    }
    __syncthreads();   // aliased region reads done before sampling overwrites

    // sampling: s_samph[(c*9+k)*18 + pp] = fp16(bilinear(x, pp, k) * mask)   (4 warps)
    int wi = tid >> 5, lane = tid & 31;
    for (int task = wi; task < 144; task += 4) {
        int pp = task / 9, k = task - pp * 9;
        float dy = s_om[pp * 27 + k];
        float dx = s_om[pp * 27 + 9 + k];
        float m  = s_om[pp * 27 + 18 + k];
        int ky = k / 3, kx = k - ky * 3;
        float py = (float)(h + ky - 1) + dy;
        float px = (float)(w0 + pp + kx - 1) + dx;
        float fy = floorf(py), fx = floorf(px);
        float wy = py - fy, wx = px - fx;
        int y0 = (int)fy, x0 = (int)fx;
        bool vy0 = (unsigned)y0 < (unsigned)Hn;
        bool vy1 = (unsigned)(y0 + 1) < (unsigned)Hn;
        bool vx0 = (unsigned)x0 < (unsigned)Wn;
        bool vx1 = (unsigned)(x0 + 1) < (unsigned)Wn;
        float w00 = (1.f - wy) * (1.f - wx) * m;
        float w01 = (1.f - wy) * wx * m;
        float w10 = wy * (1.f - wx) * m;
        float w11 = wy * wx * m;
        const float* xb = g_xT + (size_t)b * HWn * Cn
                          + ((long long)y0 * Wn + x0) * Cn;
#pragma unroll
        for (int cc = 0; cc < 2; ++cc) {
            int c = lane + cc * 32;
            float v00 = (vy0 && vx0) ? xb[c] : 0.f;
            float v01 = (vy0 && vx1) ? xb[c + Cn] : 0.f;
            float v10 = (vy1 && vx0) ? xb[c + Wn * Cn] : 0.f;
            float v11 = (vy1 && vx1) ? xb[c + Wn * Cn + Cn] : 0.f;
            float val = v00 * w00 + v01 * w01 + v10 * w10 + v11 * w11;
            s_samph[(c * 9 + k) * 18 + pp] = __float2half_rn(val);
        }
    }
    __syncthreads();

    // DCN: packed over output pairs; sample pair loaded as half2, cvt once
    u64 dp[2][2] = {{0,0},{0,0}};   // [px][out-pair]
#pragma unroll 4
    for (int r = 0; r < 576; ++r) {
        ulonglong2 w2 = *(const ulonglong2*)(g_wdcnT + r * 64 + o0);
        __half2 hh = *(const __half2*)(s_samph + r * 18 + px0);
        float2 sp = __half22float2(hh);
        u64 s0 = pk2(sp.x, sp.x);
        u64 s1 = pk2(sp.y, sp.y);
        fma2(dp[0][0], w2.x, s0); fma2(dp[0][1], w2.y, s0);
        fma2(dp[1][0], w2.x, s1); fma2(dp[1][1], w2.y, s1);
    }

    // epilogue: out = x + dcn + x*gamma + beta   (NCHW, float2 across pixel pair)
    float d[2][4], gm[2][4], bt[2][4];
#pragma unroll
    for (int px = 0; px < 2; ++px) {
        float2 q0 = up2(dp[px][0]), q1 = up2(dp[px][1]);
        d[px][0] = q0.x; d[px][1] = q0.y; d[px][2] = q1.x; d[px][3] = q1.y;
        float2 g0 = up2(gmp[px][0]), g1 = up2(gmp[px][1]);
        gm[px][0] = g0.x; gm[px][1] = g0.y; gm[px][2] = g1.x; gm[px][3] = g1.y;
        float2 b0 = up2(btp[px][0]), b1 = up2(btp[px][1]);
        bt[px][0] = b0.x; bt[px][1] = b0.y; bt[px][2] = b1.x; bt[px][3] = b1.y;
    }
    float4 xv0 = *(const float4*)(g_xT + (pixbase + px0) * 64 + o0);
    float4 xv1 = *(const float4*)(g_xT + (pixbase + px1) * 64 + o0);
    const float* xa0 = (const float*)&xv0;
    const float* xa1 = (const float*)&xv1;
#pragma unroll
    for (int j = 0; j < 4; ++j) {
        float2 rr;
        rr.x = xa0[j] + d[0][j] + xa0[j] * gm[0][j] + bt[0][j];
        rr.y = xa1[j] + d[1][j] + xa1[j] * gm[1][j] + bt[1][j];
        *(float2*)(out + ((size_t)(b * Cn + o0 + j) * Hn + h) * Wn + w0 + px0) = rr;
    }
}

// ---------------- launch ----------------
extern "C" void kernel_launch(void* const* d_in, const int* in_sizes, int n_in,
                              void* d_out, int out_size) {
    const float* x     = (const float*)d_in[0];
    const float* inter = (const float*)d_in[1];
    const float* w_off = (const float*)d_in[2];
    const float* b_off = (const float*)d_in[3];
    const float* w_dcn = (const float*)d_in[4];
    const float* wg1   = (const float*)d_in[5];
    const float* wg2   = (const float*)d_in[6];
    const float* wb1   = (const float*)d_in[7];
    const float* wb2   = (const float*)d_in[8];
    float* out = (float*)d_out;

    prep_weights<<<144, 256>>>(w_off, w_dcn, wg1, wg2, wb1, wb2);
    transpose_k<<<dim3(HWn / 32, Cn / 32, 2 * Bn), dim3(32, 8)>>>(x, inter);
    offset_conv_k<<<dim3(Wn / 64, Hn, Bn), 128>>>(x, inter, b_off);
    fused_k<<<dim3(Wn / 16, Hn, Bn), 128>>>(out);
}

// round 15
// speedup vs baseline: 1.8457x; 1.0836x over previous
#include <cuda_runtime.h>
#include <cuda_fp16.h>

#define Bn 4
#define Cn 64
#define Hn 128
#define Wn 128
#define HWn (Hn*Wn)

typedef unsigned long long u64;

// packed f32x2 helpers (sm_103a): 2 fp32 MACs per instruction, RN rounding
__device__ __forceinline__ u64 pk2(float a, float b) {
    u64 r; asm("mov.b64 %0, {%1, %2};" : "=l"(r) : "f"(a), "f"(b)); return r;
}
__device__ __forceinline__ void fma2(u64& d, u64 a, u64 b) {
    asm("fma.rn.f32x2 %0, %1, %2, %0;" : "+l"(d) : "l"(a), "l"(b));
}
__device__ __forceinline__ float2 up2(u64 v) {
    float2 r; asm("mov.b64 {%0, %1}, %2;" : "=f"(r.x), "=f"(r.y) : "l"(v)); return r;
}

// ---------------- scratch ----------------
__device__ __align__(16) float g_xT[Bn*HWn*Cn];       // x  in [B,H,W,C]
__device__ __align__(16) float g_interT[Bn*HWn*Cn];   // inter in [B,H,W,C]
__device__ __align__(16) float g_om[Bn*HWn*32];       // offsets+mask, pixel-major, pad 32
__device__ __align__(16) float g_woffT[1152*32];      // [r=cin*9+tap][o(pad32)]
__device__ __align__(16) float g_wdcnT[576*64];       // [r=c*9+k][o]
__device__ __align__(16) float g_wg1T[4096];          // [c][o]
__device__ __align__(16) float g_wg2T[4096];
__device__ __align__(16) float g_wb1T[4096];
__device__ __align__(16) float g_wb2T[4096];

// ---------------- weight prep ----------------
__global__ void prep_weights(const float* __restrict__ w_off,
                             const float* __restrict__ w_dcn,
                             const float* __restrict__ wg1, const float* __restrict__ wg2,
                             const float* __restrict__ wb1, const float* __restrict__ wb2) {
    int idx = blockIdx.x * blockDim.x + threadIdx.x;
    if (idx < 1152*32) {
        int r = idx >> 5, o = idx & 31;
        g_woffT[idx] = (o < 27) ? w_off[o*1152 + r] : 0.f;
    }
    if (idx < 576*64) {
        int r = idx >> 6, o = idx & 63;
        g_wdcnT[idx] = w_dcn[o*576 + r];
    }
    if (idx < 4096) {
        int c = idx >> 6, o = idx & 63;
        g_wg1T[idx] = wg1[o*64 + c];
        g_wg2T[idx] = wg2[o*64 + c];
        g_wb1T[idx] = wb1[o*64 + c];
        g_wb2T[idx] = wb2[o*64 + c];
    }
}

// ---------------- NCHW -> NHWC transpose (x + inter in one launch) ----------------
__global__ void transpose_k(const float* __restrict__ in_x, const float* __restrict__ in_i) {
    __shared__ float tile[32][33];
    int z = blockIdx.z;
    int b = z & 3;
    const float* in = (z & 4) ? in_i : in_x;
    float* out = (z & 4) ? g_interT : g_xT;
    int n0 = blockIdx.x * 32;
    int c0 = blockIdx.y * 32;
    int tx = threadIdx.x, ty = threadIdx.y;
    const float* src = in + (size_t)b * Cn * HWn;
    float* dst = out + (size_t)b * HWn * Cn;
#pragma unroll
    for (int i = 0; i < 32; i += 8)
        tile[ty + i][tx] = src[(size_t)(c0 + ty + i) * HWn + n0 + tx];
    __syncthreads();
#pragma unroll
    for (int i = 0; i < 32; i += 8)
        dst[(size_t)(n0 + ty + i) * Cn + c0 + tx] = tile[tx][ty + i];
}

// ---------------- offset conv (unchanged from R14) ----------------
__global__ __launch_bounds__(128) void offset_conv_k(
    const float* __restrict__ x, const float* __restrict__ inter,
    const float* __restrict__ b_off) {
    __shared__ __align__(16) float s_in[32 * 204];   // [ci][ry(3)][cx(68)] = 26112 B
    int b = blockIdx.z, h = blockIdx.y, w0 = blockIdx.x * 64;
    int tid = threadIdx.x;
    int og = tid & 7, quad = tid >> 3;
    int o0 = og * 4, p0 = quad * 4;
    u64 acc[4][2] = {{0,0},{0,0},{0,0},{0,0}};   // [px][out-pair]

    for (int half = 0; half < 2; ++half) {
        const float* src = half ? inter : x;
        for (int chunk = 0; chunk < 2; ++chunk) {
            int cbase = chunk * 32;
            __syncthreads();
            for (int idx = tid; idx < 32 * 204; idx += 128) {
                int ci = idx / 204; int rem = idx - ci * 204;
                int ry = rem / 68;  int cx = rem - ry * 68;
                int y = h - 1 + ry, xw = w0 - 1 + cx;
                float v = 0.f;
                if (cx < 66 && (unsigned)y < (unsigned)Hn && (unsigned)xw < (unsigned)Wn)
                    v = src[((size_t)(b * Cn + cbase + ci) * Hn + y) * Wn + xw];
                s_in[idx] = v;
            }
            __syncthreads();
            const float* wb = g_woffT + (half * 64 + cbase) * 288 + o0;
            for (int ci = 0; ci < 32; ++ci) {
                const float* srow = s_in + ci * 204 + p0;
                const float* wr = wb + ci * 288;
#pragma unroll
                for (int ry = 0; ry < 3; ++ry) {
                    float4 u0 = *(const float4*)(srow + ry * 68);
                    float2 u1 = *(const float2*)(srow + ry * 68 + 4);
                    u64 vp[6];
                    vp[0] = pk2(u0.x, u0.x); vp[1] = pk2(u0.y, u0.y);
                    vp[2] = pk2(u0.z, u0.z); vp[3] = pk2(u0.w, u0.w);
                    vp[4] = pk2(u1.x, u1.x); vp[5] = pk2(u1.y, u1.y);
#pragma unroll
                    for (int kx = 0; kx < 3; ++kx) {
                        ulonglong2 wp = *(const ulonglong2*)(wr + (ry * 3 + kx) * 32);
#pragma unroll
                        for (int px = 0; px < 4; ++px) {
                            fma2(acc[px][0], wp.x, vp[kx + px]);
                            fma2(acc[px][1], wp.y, vp[kx + px]);
                        }
                    }
                }
            }
        }
    }

    float bj[4];
#pragma unroll
    for (int j = 0; j < 4; ++j) bj[j] = (o0 + j < 27) ? b_off[o0 + j] : 0.f;

    size_t pixbase = ((size_t)b * Hn + h) * Wn + w0;
#pragma unroll
    for (int px = 0; px < 4; ++px) {
        float2 q0 = up2(acc[px][0]);
        float2 q1 = up2(acc[px][1]);
        float vals[4] = {q0.x, q0.y, q1.x, q1.y};
        float4 r;
        float* rv = (float*)&r;
#pragma unroll
        for (int j = 0; j < 4; ++j) {
            int o = o0 + j;
            float vv = vals[j] + bj[j];
            if (o >= 18 && o < 27) vv = 1.f / (1.f + expf(-vv));
            rv[j] = vv;
        }
        *(float4*)(g_om + (pixbase + p0 + px) * 32 + o0) = r;
    }
}

__device__ __forceinline__ float lrelu(float v) { return v >= 0.f ? v : 0.1f * v; }

// ---------------- fused: SFT chains + deformable sampling + DCN + residual ----
// 128 thr covering 32 px x 64 out: og = tid&15 (16 groups x 4 out),
// t = tid>>4 (8 t x 4 px: pixels 4t..4t+3).
// Per DCN iter/thread: 1 LDG.128 (weights) + 1 LDS.64 (4 fp16 samples) per 8 FFMA2.
// smem: s_samph [576][36] fp16 (41472 B) + s_om [32][27] f32 -> ~45 KB.
__global__ __launch_bounds__(128, 4) void fused_k(float* __restrict__ out) {
    __shared__ __align__(16) __half s_samph[576 * 36]; // [r][p(pad36)]
    __shared__ float s_om[32 * 27];
    // fp32 aliases into s_samph region (dead before sampling writes it): 25472 B used
    float* s_alias = reinterpret_cast<float*>(s_samph);
    float* s_iv = s_alias;                  // [32][65]
    float* s_t1 = s_alias + 2080;           // [32][66]
    float* s_t2 = s_alias + 2080 + 2112;    // [32][66]

    int b = blockIdx.z, h = blockIdx.y, w0 = blockIdx.x * 32;
    int tid = threadIdx.x;
    int og = tid & 15, t = tid >> 4, o0 = og * 4;
    int p0 = 4 * t;
    size_t pixbase = ((size_t)b * Hn + h) * Wn + w0;

    for (int idx = tid; idx < 32 * 27; idx += 128) {
        int pp = idx / 27, c = idx - pp * 27;
        s_om[idx] = g_om[(pixbase + pp) * 32 + c];
    }
    for (int idx = tid; idx < 32 * 64; idx += 128) {
        int pp = idx >> 6, c = idx & 63;
        s_iv[pp * 65 + c] = g_interT[(pixbase + pp) * 64 + c];
    }
    __syncthreads();

    // stage 1: t1 = lrelu(w_g1 @ iv), t2 = lrelu(w_b1 @ iv)   (4 px/thread, FFMA2)
    {
        u64 a1p[4][2] = {{0,0},{0,0},{0,0},{0,0}};
        u64 a2p[4][2] = {{0,0},{0,0},{0,0},{0,0}};
#pragma unroll 4
        for (int c = 0; c < 64; ++c) {
            ulonglong2 w1 = *(const ulonglong2*)(g_wg1T + c * 64 + o0);
            ulonglong2 w2 = *(const ulonglong2*)(g_wb1T + c * 64 + o0);
#pragma unroll
            for (int i = 0; i < 4; ++i) {
                float v = s_iv[(p0 + i) * 65 + c];
                u64 vp = pk2(v, v);
                fma2(a1p[i][0], w1.x, vp); fma2(a1p[i][1], w1.y, vp);
                fma2(a2p[i][0], w2.x, vp); fma2(a2p[i][1], w2.y, vp);
            }
        }
#pragma unroll
        for (int i = 0; i < 4; ++i) {
            float2 q0 = up2(a1p[i][0]), q1 = up2(a1p[i][1]);
            float2 r0 = up2(a2p[i][0]), r1 = up2(a2p[i][1]);
            float* t1p = s_t1 + (p0 + i) * 66 + o0;   // scalar stores (alignment)
            float* t2p = s_t2 + (p0 + i) * 66 + o0;
            t1p[0] = lrelu(q0.x); t1p[1] = lrelu(q0.y); t1p[2] = lrelu(q1.x); t1p[3] = lrelu(q1.y);
            t2p[0] = lrelu(r0.x); t2p[1] = lrelu(r0.y); t2p[2] = lrelu(r1.x); t2p[3] = lrelu(r1.y);
        }
    }
    __syncthreads();

    // stage 2: gamma = w_g2 @ t1, beta = w_b2 @ t2 (packed accumulators, kept)
    u64 gmp[4][2] = {{0,0},{0,0},{0,0},{0,0}};
    u64 btp[4][2] = {{0,0},{0,0},{0,0},{0,0}};
#pragma unroll 4
    for (int c = 0; c < 64; ++c) {
        ulonglong2 w1 = *(const ulonglong2*)(g_wg2T + c * 64 + o0);
        ulonglong2 w2 = *(const ulonglong2*)(g_wb2T + c * 64 + o0);
#pragma unroll
        for (int i = 0; i < 4; ++i) {
            float u = s_t1[(p0 + i) * 66 + c];
            float v = s_t2[(p0 + i) * 66 + c];
            u64 upk = pk2(u, u), vpk = pk2(v, v);
            fma2(gmp[i][0], w1.x, upk); fma2(gmp[i][1], w1.y, upk);
            fma2(btp[i][0], w2.x, vpk); fma2(btp[i][1], w2.y, vpk);
        }
    }
    __syncthreads();   // aliased region reads done before sampling overwrites

    // sampling: s_samph[(c*9+k)*36 + pp] = fp16(bilinear(x, pp, k) * mask)  (4 warps)
    int wi = tid >> 5, lane = tid & 31;
    for (int task = wi; task < 32 * 9; task += 4) {
        int pp = task / 9, k = task - pp * 9;
        float dy = s_om[pp * 27 + k];
        float dx = s_om[pp * 27 + 9 + k];
        float m  = s_om[pp * 27 + 18 + k];
        int ky = k / 3, kx = k - ky * 3;
        float py = (float)(h + ky - 1) + dy;
        float px = (float)(w0 + pp + kx - 1) + dx;
        float fy = floorf(py), fx = floorf(px);
        float wy = py - fy, wx = px - fx;
        int y0 = (int)fy, x0 = (int)fx;
        bool vy0 = (unsigned)y0 < (unsigned)Hn;
        bool vy1 = (unsigned)(y0 + 1) < (unsigned)Hn;
        bool vx0 = (unsigned)x0 < (unsigned)Wn;
        bool vx1 = (unsigned)(x0 + 1) < (unsigned)Wn;
        float w00 = (1.f - wy) * (1.f - wx) * m;
        float w01 = (1.f - wy) * wx * m;
        float w10 = wy * (1.f - wx) * m;
        float w11 = wy * wx * m;
        const float* xb = g_xT + (size_t)b * HWn * Cn
                          + ((long long)y0 * Wn + x0) * Cn;
#pragma unroll
        for (int cc = 0; cc < 2; ++cc) {
            int c = lane + cc * 32;
            float v00 = (vy0 && vx0) ? xb[c] : 0.f;
            float v01 = (vy0 && vx1) ? xb[c + Cn] : 0.f;
            float v10 = (vy1 && vx0) ? xb[c + Wn * Cn] : 0.f;
            float v11 = (vy1 && vx1) ? xb[c + Wn * Cn + Cn] : 0.f;
            float val = v00 * w00 + v01 * w01 + v10 * w10 + v11 * w11;
            s_samph[(c * 9 + k) * 36 + pp] = __float2half_rn(val);
        }
    }
    __syncthreads();

    // DCN: 4 px/thread. Per r: LDG.128 weights + LDS.64 (4 fp16) for 8 FFMA2.
    u64 dp[4][2] = {{0,0},{0,0},{0,0},{0,0}};   // [px][out-pair]
#pragma unroll 4
    for (int r = 0; r < 576; ++r) {
        ulonglong2 w2v = *(const ulonglong2*)(g_wdcnT + r * 64 + o0);
        uint2 hv = *(const uint2*)(s_samph + r * 36 + p0);   // 8B aligned
        float2 sp01 = __half22float2(*reinterpret_cast<const __half2*>(&hv.x));
        float2 sp23 = __half22float2(*reinterpret_cast<const __half2*>(&hv.y));
        u64 s0 = pk2(sp01.x, sp01.x);
        u64 s1 = pk2(sp01.y, sp01.y);
        u64 s2 = pk2(sp23.x, sp23.x);
        u64 s3 = pk2(sp23.y, sp23.y);
        fma2(dp[0][0], w2v.x, s0); fma2(dp[0][1], w2v.y, s0);
        fma2(dp[1][0], w2v.x, s1); fma2(dp[1][1], w2v.y, s1);
        fma2(dp[2][0], w2v.x, s2); fma2(dp[2][1], w2v.y, s2);
        fma2(dp[3][0], w2v.x, s3); fma2(dp[3][1], w2v.y, s3);
    }

    // epilogue: out = x + dcn + x*gamma + beta   (NCHW, float4 across 4 pixels)
    float dv[4][4], gv[4][4], bv[4][4], xv[4][4];
#pragma unroll
    for (int i = 0; i < 4; ++i) {
        float2 q0 = up2(dp[i][0]), q1 = up2(dp[i][1]);
        dv[i][0] = q0.x; dv[i][1] = q0.y; dv[i][2] = q1.x; dv[i][3] = q1.y;
        float2 g0 = up2(gmp[i][0]), g1 = up2(gmp[i][1]);
        gv[i][0] = g0.x; gv[i][1] = g0.y; gv[i][2] = g1.x; gv[i][3] = g1.y;
        float2 b0 = up2(btp[i][0]), b1 = up2(btp[i][1]);
        bv[i][0] = b0.x; bv[i][1] = b0.y; bv[i][2] = b1.x; bv[i][3] = b1.y;
        float4 xq = *(const float4*)(g_xT + (pixbase + p0 + i) * 64 + o0);
        xv[i][0] = xq.x; xv[i][1] = xq.y; xv[i][2] = xq.z; xv[i][3] = xq.w;
    }
#pragma unroll
    for (int j = 0; j < 4; ++j) {
        float4 rr;
        rr.x = xv[0][j] + dv[0][j] + xv[0][j] * gv[0][j] + bv[0][j];
        rr.y = xv[1][j] + dv[1][j] + xv[1][j] * gv[1][j] + bv[1][j];
        rr.z = xv[2][j] + dv[2][j] + xv[2][j] * gv[2][j] + bv[2][j];
        rr.w = xv[3][j] + dv[3][j] + xv[3][j] * gv[3][j] + bv[3][j];
        *(float4*)(out + ((size_t)(b * Cn + o0 + j) * Hn + h) * Wn + w0 + p0) = rr;
    }
}

// ---------------- launch ----------------
extern "C" void kernel_launch(void* const* d_in, const int* in_sizes, int n_in,
                              void* d_out, int out_size) {
    const float* x     = (const float*)d_in[0];
    const float* inter = (const float*)d_in[1];
    const float* w_off = (const float*)d_in[2];
    const float* b_off = (const float*)d_in[3];
    const float* w_dcn = (const float*)d_in[4];
    const float* wg1   = (const float*)d_in[5];
    const float* wg2   = (const float*)d_in[6];
    const float* wb1   = (const float*)d_in[7];
    const float* wb2   = (const float*)d_in[8];
    float* out = (float*)d_out;

    prep_weights<<<144, 256>>>(w_off, w_dcn, wg1, wg2, wb1, wb2);
    transpose_k<<<dim3(HWn / 32, Cn / 32, 2 * Bn), dim3(32, 8)>>>(x, inter);
    offset_conv_k<<<dim3(Wn / 64, Hn, Bn), 128>>>(x, inter, b_off);
    fused_k<<<dim3(Wn / 32, Hn, Bn), 128>>>(out);
}